// round 16
// baseline (speedup 1.0000x reference)
#include <cuda_runtime.h>
#include <cstdint>

// TemporalScaledDotProductforCrossAttention — GB300 fused kernel, v8.
// Persistent warp-pair STREAMS + double-buffered cp.async staging.
//   CTA = 128 thr = 2 pairs; each pair owns an independent stream of sites
//   (site = stream + it*nstreams) with 2 smem buffers: prefetch next site
//   while computing current -> staging latency fully hidden in steady state.
// Compute per site is EXACTLY R14 (best, 260us): 2 warps/site, half-warp
// variants, g=2 rows/lane, packed fma.rn.f32x2, k-outer output.
// Pair-scoped named barriers only; mask/params hoisted out of the loop.

static constexpr int STR4 = 17;    // padded float4 stride per 12-row tile
__device__ __forceinline__ constexpr int TB(int t) { return t * 204 + (t >= 4 ? 2 : 0); }
static constexpr int SITE_F4 = 6 * 204 + 2 + 204;     // 1430 float4 per site buffer
static constexpr int SMEM_BYTES = 4 * SITE_F4 * 16;   // 2 pairs x 2 buffers = 91520

__device__ __forceinline__ unsigned long long fma2(unsigned long long a,
                                                   unsigned long long b,
                                                   unsigned long long c) {
    unsigned long long d;
    asm("fma.rn.f32x2 %0, %1, %2, %3;" : "=l"(d) : "l"(a), "l"(b), "l"(c));
    return d;
}
__device__ __forceinline__ unsigned long long pack2(float x, float y) {
    unsigned long long r;
    asm("mov.b64 %0, {%1, %2};" : "=l"(r) : "f"(x), "f"(y));
    return r;
}
__device__ __forceinline__ float2 unpack2(unsigned long long v) {
    float2 r;
    asm("mov.b64 {%0, %1}, %2;" : "=f"(r.x), "=f"(r.y) : "l"(v));
    return r;
}
__device__ __forceinline__ void cp16(uint32_t smem_addr, const void* gptr) {
    asm volatile("cp.async.cg.shared.global [%0], [%1], 16;"
                 :: "r"(smem_addr), "l"(gptr));
}

__global__ __launch_bounds__(128, 2)
void tsdp_kernel(const float* __restrict__ Qf, const float* __restrict__ Kf,
                 const float* __restrict__ Vf, const float* __restrict__ Qs,
                 const float* __restrict__ Ks, const float* __restrict__ Vs,
                 const float* __restrict__ Kj, const float* __restrict__ Vfp,
                 const int* __restrict__ mask, float* __restrict__ out,
                 int nsite, int nstreams)
{
    extern __shared__ float4 T[];
    __shared__ int   smaskP[2][144];
    __shared__ float sKj[2][12], sInv[2][12];

    const int tid  = threadIdx.x;
    const int warp = tid >> 5;
    const int lane = tid & 31;
    const int pair = warp >> 1;          // stream within CTA
    const int wl   = tid & 63;           // thread index within the pair
    const int stream = blockIdx.x * 2 + pair;

    // hoisted once per stream: mask + flow-speed params
    for (int i = wl; i < 144; i += 64) smaskP[pair][i] = mask[i];
    if (wl < 12) {
        sKj[pair][wl]  = __ldg(Kj + wl);
        sInv[pair][wl] = 1.0f / (__ldg(Vfp + wl) + 1e-5f);
    }

    float4* bufs = T + pair * 2 * SITE_F4;

    // ---- prologue: stage first site into buffer 0 ----
    int site = stream;
    int cur  = 0;
    if (site < nsite) {
        const uint32_t sb = (uint32_t)__cvta_generic_to_shared(bufs);
        const long long gb = (long long)site * 192;
        #pragma unroll
        for (int rep = 0; rep < 3; rep++) {
            int f = wl + rep * 64;
            int r = f >> 4, cc = f & 15;
            uint32_t sa = sb + (uint32_t)(r * STR4 + cc) * 16u;
            long long g = gb + f;
            cp16(sa + TB(0) * 16u, (const float4*)Qf + g);
            cp16(sa + TB(1) * 16u, (const float4*)Kf + g);
            cp16(sa + TB(2) * 16u, (const float4*)Vf + g);
            cp16(sa + TB(3) * 16u, (const float4*)Qs + g);
            cp16(sa + TB(4) * 16u, (const float4*)Ks + g);
            cp16(sa + TB(5) * 16u, (const float4*)Vs + g);
        }
    }
    asm volatile("cp.async.commit_group;" ::: "memory");

    while (site < nsite) {
        // ---- prefetch next site into the alternate buffer ----
        const int next = site + nstreams;
        if (next < nsite) {
            const uint32_t sb = (uint32_t)__cvta_generic_to_shared(bufs + (cur ^ 1) * SITE_F4);
            const long long gb = (long long)next * 192;
            #pragma unroll
            for (int rep = 0; rep < 3; rep++) {
                int f = wl + rep * 64;
                int r = f >> 4, cc = f & 15;
                uint32_t sa = sb + (uint32_t)(r * STR4 + cc) * 16u;
                long long g = gb + f;
                cp16(sa + TB(0) * 16u, (const float4*)Qf + g);
                cp16(sa + TB(1) * 16u, (const float4*)Kf + g);
                cp16(sa + TB(2) * 16u, (const float4*)Vf + g);
                cp16(sa + TB(3) * 16u, (const float4*)Qs + g);
                cp16(sa + TB(4) * 16u, (const float4*)Ks + g);
                cp16(sa + TB(5) * 16u, (const float4*)Vs + g);
            }
        }
        asm volatile("cp.async.commit_group;" ::: "memory");
        asm volatile("cp.async.wait_group 1;" ::: "memory");   // current site ready
        asm volatile("bar.sync %0, 64;" :: "r"(1 + pair) : "memory");

        float4* Ts = bufs + cur * SITE_F4;

        // ---- build flow-speed tile (QFS) from resident QS tile ----
        #pragma unroll
        for (int rep = 0; rep < 3; rep++) {
            int f = wl + rep * 64;
            int r = f >> 4, cc = f & 15;
            int i17 = r * STR4 + cc;
            float4 v = Ts[TB(3) + i17];
            float kj  = sKj[pair][r];
            float inv = sInv[pair][r];
            float4 w;
            w.x = kj * (v.x - (v.x * v.x) * inv);
            w.y = kj * (v.y - (v.y * v.y) * inv);
            w.z = kj * (v.z - (v.z * v.z) * inv);
            w.w = kj * (v.w - (v.w * v.w) * inv);
            Ts[TB(6) + i17] = w;
        }
        asm volatile("bar.sync %0, 64;" :: "r"(1 + pair) : "memory");

        // ---- compute (R14 structure, lanes 0..23 of each warp) ----
        if (lane < 24) {
            const int vp  = warp & 1;               // 0: ff+fs, 1: sf+ss
            const int sub = (lane >= 12) ? 1 : 0;
            const int l   = lane - 12 * sub;
            const int qp  = l >> 1;
            const int h   = l & 1;
            const int q0  = 2 * qp, q1 = q0 + 1;
            const int rot = 4 * h;

            int aT, bT, vT, outq;
            if (vp == 0) {
                if (!sub) { aT = 0; bT = 1; vT = 2; outq = 0; }   // ff
                else      { aT = 1; bT = 6; vT = 2; outq = 1; }   // fs
            } else {
                if (!sub) { aT = 4; bT = 0; vT = 5; outq = 2; }   // sf
                else      { aT = 3; bT = 4; vT = 5; outq = 3; }   // ss
            }
            const ulonglong2* A2 = (const ulonglong2*)(Ts + TB(aT));
            const ulonglong2* B2 = (const ulonglong2*)(Ts + TB(bT));
            const ulonglong2* V2 = (const ulonglong2*)(Ts + TB(vT));
            const int* smask = smaskP[pair];

            float s0[12], s1[12];
            #pragma unroll
            for (int k = 0; k < 12; k++) { s0[k] = 0.0f; s1[k] = 0.0f; }

            #pragma unroll
            for (int ch = 0; ch < 2; ch++) {
                ulonglong2 a0[4], a1[4];
                int jj[4];
                #pragma unroll
                for (int i = 0; i < 4; i++) {
                    jj[i] = (ch * 4 + i + rot) & 7;
                    a0[i] = A2[q0 * STR4 + h * 8 + jj[i]];
                    a1[i] = A2[q1 * STR4 + h * 8 + jj[i]];
                }
                #pragma unroll
                for (int k = 0; k < 12; k++) {
                    unsigned long long acc0 = 0ULL, acc1 = 0ULL;
                    #pragma unroll
                    for (int i = 0; i < 4; i++) {
                        ulonglong2 b = B2[k * STR4 + h * 8 + jj[i]];
                        acc0 = fma2(a0[i].x, b.x, acc0);
                        acc0 = fma2(a0[i].y, b.y, acc0);
                        acc1 = fma2(a1[i].x, b.x, acc1);
                        acc1 = fma2(a1[i].y, b.y, acc1);
                    }
                    float2 p0 = unpack2(acc0), p1 = unpack2(acc1);
                    s0[k] += p0.x + p0.y;
                    s1[k] += p1.x + p1.y;
                }
            }

            #pragma unroll
            for (int k = 0; k < 12; k++) {
                float v0 = s0[k] + __shfl_xor_sync(0x00ffffffu, s0[k], 1);
                float v1 = s1[k] + __shfl_xor_sync(0x00ffffffu, s1[k], 1);
                s0[k] = (smask[q0 * 12 + k] == 1) ? -1e9f : v0 * 0.125f;
                s1[k] = (smask[q1 * 12 + k] == 1) ? -1e9f : v1 * 0.125f;
            }

            float mx0 = s0[0], mx1 = s1[0];
            #pragma unroll
            for (int k = 1; k < 12; k++) { mx0 = fmaxf(mx0, s0[k]); mx1 = fmaxf(mx1, s1[k]); }
            float sum0 = 0.f, sum1 = 0.f;
            #pragma unroll
            for (int k = 0; k < 12; k++) {
                s0[k] = __expf(s0[k] - mx0); sum0 += s0[k];
                s1[k] = __expf(s1[k] - mx1); sum1 += s1[k];
            }
            const float rs0 = 1.0f / sum0, rs1 = 1.0f / sum1;
            #pragma unroll
            for (int k = 0; k < 12; k++) { s0[k] *= rs0; s1[k] *= rs1; }

            ulonglong2 c0[8], c1[8];
            #pragma unroll
            for (int i = 0; i < 8; i++) { c0[i].x = c0[i].y = 0ULL; c1[i].x = c1[i].y = 0ULL; }

            #pragma unroll
            for (int k = 0; k < 12; k++) {
                unsigned long long z0p = pack2(s0[k], s0[k]);
                unsigned long long z1p = pack2(s1[k], s1[k]);
                #pragma unroll
                for (int i = 0; i < 8; i++) {
                    ulonglong2 v = V2[k * STR4 + h * 8 + ((i + rot) & 7)];
                    c0[i].x = fma2(z0p, v.x, c0[i].x);
                    c0[i].y = fma2(z0p, v.y, c0[i].y);
                    c1[i].x = fma2(z1p, v.x, c1[i].x);
                    c1[i].y = fma2(z1p, v.y, c1[i].y);
                }
            }

            float4* ob = (float4*)out + ((long long)outq * nsite + site) * 192 + h * 8;
            float4* o0 = ob + q0 * 16;
            float4* o1 = ob + q1 * 16;
            #pragma unroll
            for (int i = 0; i < 8; i++) {
                int j = (i + rot) & 7;
                float2 lo0 = unpack2(c0[i].x), hi0 = unpack2(c0[i].y);
                float2 lo1 = unpack2(c1[i].x), hi1 = unpack2(c1[i].y);
                o0[j] = make_float4(lo0.x, lo0.y, hi0.x, hi0.y);
                o1[j] = make_float4(lo1.x, lo1.y, hi1.x, hi1.y);
            }
        }
        // protect the just-computed buffer before the next prefetch overwrites it
        asm volatile("bar.sync %0, 64;" :: "r"(1 + pair) : "memory");

        site = next;
        cur ^= 1;
    }
}

extern "C" void kernel_launch(void* const* d_in, const int* in_sizes, int n_in,
                              void* d_out, int out_size) {
    const int nsite = in_sizes[0] / 768;   // B*H*L1 = 39296
    const int grid  = 296;                 // 2 streams/CTA -> 592 streams
    const int nstreams = grid * 2;
    cudaFuncSetAttribute(tsdp_kernel,
                         cudaFuncAttributeMaxDynamicSharedMemorySize, SMEM_BYTES);
    tsdp_kernel<<<grid, 128, SMEM_BYTES>>>(
        (const float*)d_in[0], (const float*)d_in[1], (const float*)d_in[2],
        (const float*)d_in[3], (const float*)d_in[4], (const float*)d_in[5],
        (const float*)d_in[6], (const float*)d_in[7],
        (const int*)d_in[8],
        (float*)d_out, nsite, nstreams);
}